// round 1
// baseline (speedup 1.0000x reference)
#include <cuda_runtime.h>
#include <math.h>

// Problem constants
#define S_TOK   1024
#define HID     768
#define NE      64
#define TK      8
#define CAPMAX  256
#define I1      3072
#define I2      6144

// GEMM tiling
#define BM 128
#define BN 64
#define BK 16
#define NTHREADS 256

// ---------------- device scratch (static, allocation-free) ----------------
__device__ __align__(16)  float g_topw[S_TOK][TK];     // router prob for chosen expert
__device__ __align__(16)  int   g_topi[S_TOK][TK];     // chosen expert id
__device__ __align__(16)  int   g_slot[S_TOK][TK];     // slot within expert, or -1
__device__ __align__(16)  int   g_ecount[NE];          // used slots per expert
__device__ __align__(16)  int   g_etok[NE][CAPMAX];    // token id per (expert, slot)
__device__ __align__(256) float g_sh_gated[S_TOK][I1];        // 12.6 MB
__device__ __align__(256) float g_ex_gated[NE][CAPMAX][I1];   // 201 MB
__device__ __align__(256) float g_ex_out[NE][CAPMAX][HID];    // 50 MB

// ---------------- gating: logits + top-8 + normalized weights -------------
__global__ void gating_kernel(const float* __restrict__ x,
                              const float* __restrict__ wg) {
    int s = blockIdx.x;
    __shared__ float xs[HID];
    __shared__ float logits_s[NE];
    int tid = threadIdx.x;

    for (int i = tid; i < HID; i += 256) xs[i] = x[(size_t)s * HID + i];
    __syncthreads();

    // 4 threads per expert compute the dot product
    int e   = tid >> 2;
    int sub = tid & 3;
    const float* w = wg + (size_t)e * HID;
    float acc = 0.f;
    for (int i = sub; i < HID; i += 4) acc += xs[i] * w[i];
    acc += __shfl_down_sync(0xffffffffu, acc, 2);
    acc += __shfl_down_sync(0xffffffffu, acc, 1);
    if (sub == 0) logits_s[e] = acc;
    __syncthreads();

    if (tid < 32) {
        float v0 = logits_s[tid];
        float v1 = logits_s[tid + 32];
        float tv[TK];
        int   tix[TK];
#pragma unroll
        for (int r = 0; r < TK; r++) {
            float bv; int bi;
            if (v0 >= v1) { bv = v0; bi = tid; }        // tie -> lower index
            else          { bv = v1; bi = tid + 32; }
#pragma unroll
            for (int off = 16; off > 0; off >>= 1) {
                float ov = __shfl_down_sync(0xffffffffu, bv, off);
                int   oi = __shfl_down_sync(0xffffffffu, bi, off);
                if (ov > bv || (ov == bv && oi < bi)) { bv = ov; bi = oi; }
            }
            bv = __shfl_sync(0xffffffffu, bv, 0);
            bi = __shfl_sync(0xffffffffu, bi, 0);
            if (bi == tid)      v0 = -INFINITY;
            if (bi == tid + 32) v1 = -INFINITY;
            tv[r]  = bv;
            tix[r] = bi;
        }
        if (tid == 0) {
            // router weight = exp(l - max) / sum_topk exp(l - max)
            float m = tv[0];
            float wv[TK];
            float D = 0.f;
#pragma unroll
            for (int r = 0; r < TK; r++) { wv[r] = expf(tv[r] - m); D += wv[r]; }
            D = fmaxf(D, 1.1920929e-7f);
#pragma unroll
            for (int r = 0; r < TK; r++) {
                g_topw[s][r] = wv[r] / D;
                g_topi[s][r] = tix[r];
            }
        }
    }
}

// ---------------- priority / capacity assignment (expert-major, k-major) --
__global__ void priority_kernel(const int* __restrict__ capacity) {
    int e    = blockIdx.x;
    int lane = threadIdx.x;
    int cap  = capacity[0];
    if (cap > CAPMAX) cap = CAPMAX;
    if (cap < 0) cap = 0;

    int offset = 0;
    for (int base = 0; base < S_TOK * TK; base += 32) {
        int p = base + lane;
        int k = p / S_TOK;
        int s = p - k * S_TOK;
        bool match = (g_topi[s][k] == e);
        unsigned mask = __ballot_sync(0xffffffffu, match);
        if (match) {
            int c = offset + __popc(mask & ((1u << lane) - 1u));
            if (c < cap) {
                g_slot[s][k]  = c;
                g_etok[e][c]  = s;
            } else {
                g_slot[s][k] = -1;
            }
        }
        offset += __popc(mask);
    }
    if (lane == 0) g_ecount[e] = (offset < cap) ? offset : cap;
}

// ---------------- GEMM1 + SwiGLU: Out[m,n] = (A.W[n]) * silu(A.W[n+I1]) ---
// A: [*, HID] row-major (optionally gathered rows), W: [I2, HID] row-major.
__global__ __launch_bounds__(NTHREADS)
void gemm1_kernel(const float* __restrict__ X,
                  const float* __restrict__ W,
                  int shared_mode) {
    __shared__ float As [BK][BM];
    __shared__ float Bs1[BK][BN];
    __shared__ float Bs2[BK][BN];

    int e = blockIdx.z;
    int M;
    const int*   gather;
    const float* Wp;
    float*       Out;
    if (shared_mode) {
        M = S_TOK; gather = nullptr; Wp = W; Out = &g_sh_gated[0][0];
    } else {
        M = g_ecount[e];
        gather = g_etok[e];
        Wp  = W + (size_t)e * I2 * HID;
        Out = &g_ex_gated[e][0][0];
    }
    int m0 = blockIdx.y * BM;
    if (m0 >= M) return;
    int n0 = blockIdx.x * BN;

    int tid = threadIdx.x;
    int tx = tid & 15;   // 0..15 -> 4 output cols each
    int ty = tid >> 4;   // 0..15 -> 8 output rows each

    float acc1[8][4], acc2[8][4];
#pragma unroll
    for (int i = 0; i < 8; i++)
#pragma unroll
        for (int j = 0; j < 4; j++) { acc1[i][j] = 0.f; acc2[i][j] = 0.f; }

    // A loader mapping: two float4 per thread
    int arow0 = tid >> 2;           // 0..63
    int arow1 = (tid + 256) >> 2;   // 64..127
    int aseg  = tid & 3;
    long grow0 = -1, grow1 = -1;
    {
        int mm0 = m0 + arow0, mm1 = m0 + arow1;
        if (mm0 < M) grow0 = gather ? gather[mm0] : mm0;
        if (mm1 < M) grow1 = gather ? gather[mm1] : mm1;
    }
    // B loader mapping: one float4 per thread per buffer
    int brow = tid >> 2;            // 0..63
    int bseg = tid & 3;

    for (int k0 = 0; k0 < HID; k0 += BK) {
        float4 va0 = make_float4(0.f, 0.f, 0.f, 0.f), va1 = va0;
        if (grow0 >= 0) va0 = *(const float4*)&X[grow0 * HID + k0 + aseg * 4];
        if (grow1 >= 0) va1 = *(const float4*)&X[grow1 * HID + k0 + aseg * 4];
        As[aseg*4+0][arow0] = va0.x; As[aseg*4+1][arow0] = va0.y;
        As[aseg*4+2][arow0] = va0.z; As[aseg*4+3][arow0] = va0.w;
        As[aseg*4+0][arow1] = va1.x; As[aseg*4+1][arow1] = va1.y;
        As[aseg*4+2][arow1] = va1.z; As[aseg*4+3][arow1] = va1.w;

        float4 vb1 = *(const float4*)&Wp[(size_t)(n0 + brow)      * HID + k0 + bseg * 4];
        float4 vb2 = *(const float4*)&Wp[(size_t)(n0 + brow + I1) * HID + k0 + bseg * 4];
        Bs1[bseg*4+0][brow] = vb1.x; Bs1[bseg*4+1][brow] = vb1.y;
        Bs1[bseg*4+2][brow] = vb1.z; Bs1[bseg*4+3][brow] = vb1.w;
        Bs2[bseg*4+0][brow] = vb2.x; Bs2[bseg*4+1][brow] = vb2.y;
        Bs2[bseg*4+2][brow] = vb2.z; Bs2[bseg*4+3][brow] = vb2.w;
        __syncthreads();

#pragma unroll
        for (int kk = 0; kk < BK; kk++) {
            float a[8], b1[4], b2[4];
#pragma unroll
            for (int i = 0; i < 8; i++) a[i] = As[kk][ty * 8 + i];
#pragma unroll
            for (int j = 0; j < 4; j++) { b1[j] = Bs1[kk][tx * 4 + j]; b2[j] = Bs2[kk][tx * 4 + j]; }
#pragma unroll
            for (int i = 0; i < 8; i++)
#pragma unroll
                for (int j = 0; j < 4; j++) {
                    acc1[i][j] += a[i] * b1[j];
                    acc2[i][j] += a[i] * b2[j];
                }
        }
        __syncthreads();
    }

#pragma unroll
    for (int i = 0; i < 8; i++) {
        int m = m0 + ty * 8 + i;
        if (m >= M) continue;
#pragma unroll
        for (int j = 0; j < 4; j++) {
            int n = n0 + tx * 4 + j;
            float g2  = acc2[i][j];
            float sig = 1.f / (1.f + expf(-g2));
            Out[(size_t)m * I1 + n] = acc1[i][j] * (g2 * sig);
        }
    }
}

// ---------------- GEMM2: Out[m,n] = G[m,:I1] . W[n,:I1] -------------------
__global__ __launch_bounds__(NTHREADS)
void gemm2_kernel(const float* __restrict__ Wd,
                  float* __restrict__ dout,
                  int shared_mode) {
    __shared__ float Gs[BK][BM];
    __shared__ float Bs[BK][BN];

    int e = blockIdx.z;
    int M;
    const float* G;
    const float* Wp;
    float*       Out;
    if (shared_mode) {
        M = S_TOK; G = &g_sh_gated[0][0]; Wp = Wd; Out = dout;
    } else {
        M = g_ecount[e];
        G   = &g_ex_gated[e][0][0];
        Wp  = Wd + (size_t)e * HID * I1;
        Out = &g_ex_out[e][0][0];
    }
    int m0 = blockIdx.y * BM;
    if (m0 >= M) return;
    int n0 = blockIdx.x * BN;

    int tid = threadIdx.x;
    int tx = tid & 15;
    int ty = tid >> 4;

    float acc[8][4];
#pragma unroll
    for (int i = 0; i < 8; i++)
#pragma unroll
        for (int j = 0; j < 4; j++) acc[i][j] = 0.f;

    int arow0 = tid >> 2;
    int arow1 = (tid + 256) >> 2;
    int aseg  = tid & 3;
    bool v0 = (m0 + arow0) < M;
    bool v1 = (m0 + arow1) < M;
    int brow = tid >> 2, bseg = tid & 3;

    for (int k0 = 0; k0 < I1; k0 += BK) {
        float4 va0 = make_float4(0.f, 0.f, 0.f, 0.f), va1 = va0;
        if (v0) va0 = *(const float4*)&G[(size_t)(m0 + arow0) * I1 + k0 + aseg * 4];
        if (v1) va1 = *(const float4*)&G[(size_t)(m0 + arow1) * I1 + k0 + aseg * 4];
        Gs[aseg*4+0][arow0] = va0.x; Gs[aseg*4+1][arow0] = va0.y;
        Gs[aseg*4+2][arow0] = va0.z; Gs[aseg*4+3][arow0] = va0.w;
        Gs[aseg*4+0][arow1] = va1.x; Gs[aseg*4+1][arow1] = va1.y;
        Gs[aseg*4+2][arow1] = va1.z; Gs[aseg*4+3][arow1] = va1.w;

        float4 vb = *(const float4*)&Wp[(size_t)(n0 + brow) * I1 + k0 + bseg * 4];
        Bs[bseg*4+0][brow] = vb.x; Bs[bseg*4+1][brow] = vb.y;
        Bs[bseg*4+2][brow] = vb.z; Bs[bseg*4+3][brow] = vb.w;
        __syncthreads();

#pragma unroll
        for (int kk = 0; kk < BK; kk++) {
            float a[8], b[4];
#pragma unroll
            for (int i = 0; i < 8; i++) a[i] = Gs[kk][ty * 8 + i];
#pragma unroll
            for (int j = 0; j < 4; j++) b[j] = Bs[kk][tx * 4 + j];
#pragma unroll
            for (int i = 0; i < 8; i++)
#pragma unroll
                for (int j = 0; j < 4; j++) acc[i][j] += a[i] * b[j];
        }
        __syncthreads();
    }

#pragma unroll
    for (int i = 0; i < 8; i++) {
        int m = m0 + ty * 8 + i;
        if (m >= M) continue;
#pragma unroll
        for (int j = 0; j < 4; j++) {
            int n = n0 + tx * 4 + j;
            Out[(size_t)m * HID + n] = acc[i][j];
        }
    }
}

// ---------------- combine: out[s] = shared[s] + sum_k w * expert_out ------
__global__ void combine_kernel(float* __restrict__ out) {
    int s   = blockIdx.x;
    int tid = threadIdx.x;
    __shared__ int   ke[TK];
    __shared__ int   kc[TK];
    __shared__ float kw[TK];
    if (tid < TK) {
        ke[tid] = g_topi[s][tid];
        kc[tid] = g_slot[s][tid];
        kw[tid] = g_topw[s][tid];
    }
    __syncthreads();
    for (int h = tid; h < HID; h += 256) {
        float acc = out[(size_t)s * HID + h];
#pragma unroll
        for (int k = 0; k < TK; k++) {
            int c = kc[k];
            if (c >= 0) acc += kw[k] * g_ex_out[ke[k]][c][h];
        }
        out[(size_t)s * HID + h] = acc;
    }
}

// ---------------------------------------------------------------------------
extern "C" void kernel_launch(void* const* d_in, const int* in_sizes, int n_in,
                              void* d_out, int out_size) {
    const float* x      = (const float*)d_in[0];   // [1,1024,768]
    const float* w_gu   = (const float*)d_in[1];   // [6144,768]
    const float* w_down = (const float*)d_in[2];   // [768,3072]
    const float* wg     = (const float*)d_in[3];   // [64,768]
    const float* w1     = (const float*)d_in[4];   // [64,6144,768]
    const float* w2     = (const float*)d_in[5];   // [64,768,3072]
    const int*   cap    = (const int*)d_in[6];     // scalar
    float* out = (float*)d_out;

    gating_kernel<<<S_TOK, 256>>>(x, wg);
    priority_kernel<<<NE, 32>>>(cap);

    // shared MLP GEMM1 (+SwiGLU)
    {
        dim3 g(I1 / BN, S_TOK / BM, 1);          // 48 x 8
        gemm1_kernel<<<g, NTHREADS>>>(x, w_gu, 1);
    }
    // expert GEMM1 (+SwiGLU), gathered rows
    {
        dim3 g(I1 / BN, (CAPMAX + BM - 1) / BM, NE);  // 48 x 2 x 64
        gemm1_kernel<<<g, NTHREADS>>>(x, w1, 0);
    }
    // shared MLP GEMM2 -> writes base output
    {
        dim3 g(HID / BN, S_TOK / BM, 1);         // 12 x 8
        gemm2_kernel<<<g, NTHREADS>>>(w_down, out, 1);
    }
    // expert GEMM2 -> per-expert outputs
    {
        dim3 g(HID / BN, (CAPMAX + BM - 1) / BM, NE); // 12 x 2 x 64
        gemm2_kernel<<<g, NTHREADS>>>(w2, out, 0);
    }
    // combine
    combine_kernel<<<S_TOK, 256>>>(out);
}

// round 3
// speedup vs baseline: 2.2746x; 2.2746x over previous
#include <cuda_runtime.h>
#include <cstdint>
#include <math.h>

// ---------------- problem constants ----------------
#define S_TOK   1024
#define HID     768
#define NE      64
#define TK      8
#define CAPMAX  256
#define I1      3072
#define I2      6144

// ---------------- GEMM tiling ----------------
#define BM   256
#define BK   32
#define PR   36                       // padded row length (floats)
#define A_BYTES (BM * PR * 4)         // 36864
#define B_BYTES (128 * PR * 4)        // 18432 (gemm1 uses 128 rows, gemm2 64)
#define STG     (A_BYTES + B_BYTES)   // 55296
#define SMEM_BYTES (2 * STG)          // 110592
#define NC1 (HID / BK)                // 24
#define NC2 (I1 / BK)                 // 96

// ---------------- device scratch ----------------
__device__ __align__(16)  float g_topw[S_TOK][TK];
__device__ __align__(16)  int   g_topi[S_TOK][TK];
__device__ __align__(16)  int   g_slot[S_TOK][TK];
__device__ __align__(16)  int   g_ecount[NE];
__device__ __align__(16)  int   g_etok[NE][CAPMAX];
__device__ __align__(256) float g_sh_gated[S_TOK][I1];
__device__ __align__(256) float g_ex_gated[NE][CAPMAX][I1];
__device__ __align__(256) float g_ex_out[NE][CAPMAX][HID];

// ---------------- helpers ----------------
__device__ __forceinline__ uint32_t smem_u32(const void* p) {
    uint32_t a;
    asm("{ .reg .u64 t; cvta.to.shared.u64 t, %1; cvt.u32.u64 %0, t; }" : "=r"(a) : "l"(p));
    return a;
}
__device__ __forceinline__ uint32_t lds_u32(uint32_t addr) {
    uint32_t v;
    asm volatile("ld.shared.b32 %0, [%1];" : "=r"(v) : "r"(addr));
    return v;
}
// convert 4 fp32 -> tf32 (RNA) and store 16B to smem
__device__ __forceinline__ void cvt_sts(uint32_t addr, float4 v) {
    uint32_t a, b, c, d;
    asm volatile("cvt.rna.tf32.f32 %0, %1;" : "=r"(a) : "f"(v.x));
    asm volatile("cvt.rna.tf32.f32 %0, %1;" : "=r"(b) : "f"(v.y));
    asm volatile("cvt.rna.tf32.f32 %0, %1;" : "=r"(c) : "f"(v.z));
    asm volatile("cvt.rna.tf32.f32 %0, %1;" : "=r"(d) : "f"(v.w));
    asm volatile("st.shared.v4.b32 [%0], {%1, %2, %3, %4};"
                 :: "r"(addr), "r"(a), "r"(b), "r"(c), "r"(d) : "memory");
}
#define MMA_TF32(c, a, b0v, b1v) \
    asm volatile("mma.sync.aligned.m16n8k8.row.col.f32.tf32.tf32.f32 " \
        "{%0,%1,%2,%3}, {%4,%5,%6,%7}, {%8,%9}, {%0,%1,%2,%3};" \
        : "+f"((c)[0]), "+f"((c)[1]), "+f"((c)[2]), "+f"((c)[3]) \
        : "r"((a)[0]), "r"((a)[1]), "r"((a)[2]), "r"((a)[3]), "r"(b0v), "r"(b1v))

extern __shared__ char dsm[];

// ---------------- gating ----------------
__global__ void gating_kernel(const float* __restrict__ x,
                              const float* __restrict__ wg) {
    int s = blockIdx.x;
    __shared__ float xs[HID];
    __shared__ float logits_s[NE];
    int tid = threadIdx.x;

    for (int i = tid; i < HID; i += 256) xs[i] = x[(size_t)s * HID + i];
    __syncthreads();

    int e = tid >> 2, sub = tid & 3;
    const float* w = wg + (size_t)e * HID;
    float acc = 0.f;
    for (int i = sub; i < HID; i += 4) acc += xs[i] * w[i];
    acc += __shfl_down_sync(0xffffffffu, acc, 2);
    acc += __shfl_down_sync(0xffffffffu, acc, 1);
    if (sub == 0) logits_s[e] = acc;
    __syncthreads();

    if (tid < 32) {
        float v0 = logits_s[tid];
        float v1 = logits_s[tid + 32];
        float tv[TK]; int tix[TK];
#pragma unroll
        for (int r = 0; r < TK; r++) {
            float bv; int bi;
            if (v0 >= v1) { bv = v0; bi = tid; }
            else          { bv = v1; bi = tid + 32; }
#pragma unroll
            for (int off = 16; off > 0; off >>= 1) {
                float ov = __shfl_down_sync(0xffffffffu, bv, off);
                int   oi = __shfl_down_sync(0xffffffffu, bi, off);
                if (ov > bv || (ov == bv && oi < bi)) { bv = ov; bi = oi; }
            }
            bv = __shfl_sync(0xffffffffu, bv, 0);
            bi = __shfl_sync(0xffffffffu, bi, 0);
            if (bi == tid)      v0 = -INFINITY;
            if (bi == tid + 32) v1 = -INFINITY;
            tv[r] = bv; tix[r] = bi;
        }
        if (tid == 0) {
            float m = tv[0], wv[TK], D = 0.f;
#pragma unroll
            for (int r = 0; r < TK; r++) { wv[r] = expf(tv[r] - m); D += wv[r]; }
            D = fmaxf(D, 1.1920929e-7f);
#pragma unroll
            for (int r = 0; r < TK; r++) { g_topw[s][r] = wv[r] / D; g_topi[s][r] = tix[r]; }
        }
    }
}

// ---------------- priority ----------------
__global__ void priority_kernel(const int* __restrict__ capacity) {
    int e = blockIdx.x, lane = threadIdx.x;
    int cap = capacity[0];
    if (cap > CAPMAX) cap = CAPMAX;
    if (cap < 0) cap = 0;

    int offset = 0;
    for (int base = 0; base < S_TOK * TK; base += 32) {
        int p = base + lane;
        int k = p / S_TOK;
        int s = p - k * S_TOK;
        bool match = (g_topi[s][k] == e);
        unsigned mask = __ballot_sync(0xffffffffu, match);
        if (match) {
            int c = offset + __popc(mask & ((1u << lane) - 1u));
            if (c < cap) { g_slot[s][k] = c; g_etok[e][c] = s; }
            else         { g_slot[s][k] = -1; }
        }
        offset += __popc(mask);
    }
    if (lane == 0) g_ecount[e] = (offset < cap) ? offset : cap;
}

// ---------------- GEMM1 (tf32 mma.sync) + fused SwiGLU ----------------
// Block: M=256 rows of A, pair-width 64 output cols (g1 & g2 each 64).
// B SMEM rows 0..63 = W[n0+r], rows 64..127 = W[n0+I1+r].
__global__ __launch_bounds__(256, 1)
void gemm1_mma(const float* __restrict__ X, const float* __restrict__ W, int shared_mode) {
    int e = blockIdx.z;
    int M; const int* gather; const float* Wp; float* Out;
    if (shared_mode) { M = S_TOK; gather = nullptr; Wp = W; Out = &g_sh_gated[0][0]; }
    else {
        M = g_ecount[e]; gather = g_etok[e];
        Wp = W + (size_t)e * I2 * HID; Out = &g_ex_gated[e][0][0];
    }
    int m0 = blockIdx.y * BM;
    if (m0 >= M) return;
    int n0 = blockIdx.x * 64;

    uint32_t sb = smem_u32(dsm);
    int t = threadIdx.x, lane = t & 31, wid = t >> 5;
    int wm = wid >> 2, wn = wid & 3;     // 2 x 4 warp grid
    int lq = lane >> 2, lr = lane & 3;

    // loader indices
    int kseg = t & 7;           // 0..7 -> k offset kseg*4
    int r8   = t >> 3;          // 0..31

    // A global pointers (8 passes of 32 rows)
    const float* ap[8];
#pragma unroll
    for (int p = 0; p < 8; p++) {
        int m = m0 + p * 32 + r8;
        ap[p] = (m < M) ? (X + (size_t)(gather ? gather[m] : m) * HID + kseg * 4) : nullptr;
    }
    // B global pointers (4 passes of 32 rows; rows<64 -> g1, else g2)
    const float* bp[4];
#pragma unroll
    for (int p = 0; p < 4; p++) {
        int row = p * 32 + r8;
        int wr = (row < 64) ? (n0 + row) : (n0 + row - 64 + I1);
        bp[p] = Wp + (size_t)wr * HID + kseg * 4;
    }

    float acc1[8][2][4], acc2[8][2][4];
#pragma unroll
    for (int mt = 0; mt < 8; mt++)
#pragma unroll
        for (int nt = 0; nt < 2; nt++)
#pragma unroll
            for (int i = 0; i < 4; i++) { acc1[mt][nt][i] = 0.f; acc2[mt][nt][i] = 0.f; }

    float4 va[8], vbr[4];
    uint32_t a_sts = (uint32_t)(r8 * PR + kseg * 4) * 4;   // within-pass base (add p*32*PR*4)

    // prologue: chunk 0 -> buf 0
#pragma unroll
    for (int p = 0; p < 8; p++)
        va[p] = ap[p] ? *(const float4*)(ap[p]) : make_float4(0.f, 0.f, 0.f, 0.f);
#pragma unroll
    for (int p = 0; p < 4; p++) vbr[p] = *(const float4*)(bp[p]);
    {
        uint32_t Ab = sb, Bb = sb + A_BYTES;
#pragma unroll
        for (int p = 0; p < 8; p++) cvt_sts(Ab + p * 32 * PR * 4 + a_sts, va[p]);
#pragma unroll
        for (int p = 0; p < 4; p++) cvt_sts(Bb + p * 32 * PR * 4 + a_sts, vbr[p]);
    }
    __syncthreads();

#pragma unroll 1
    for (int kc = 0; kc < NC1; kc++) {
        int buf = kc & 1;
        // prefetch next chunk
        if (kc + 1 < NC1) {
            int ko = (kc + 1) * BK;
#pragma unroll
            for (int p = 0; p < 8; p++)
                va[p] = ap[p] ? *(const float4*)(ap[p] + ko) : make_float4(0.f, 0.f, 0.f, 0.f);
#pragma unroll
            for (int p = 0; p < 4; p++) vbr[p] = *(const float4*)(bp[p] + ko);
        }
        // compute from smem[buf]
        uint32_t Ab = sb + buf * STG;
        uint32_t Bb = Ab + A_BYTES;
#pragma unroll
        for (int ks = 0; ks < 4; ks++) {
            uint32_t kcol = (uint32_t)(ks * 8 + lr) * 4;
            uint32_t a[8][4];
#pragma unroll
            for (int mt = 0; mt < 8; mt++) {
                uint32_t base = Ab + (uint32_t)((wm * 128 + mt * 16 + lq) * PR) * 4 + kcol;
                a[mt][0] = lds_u32(base);
                a[mt][1] = lds_u32(base + 8 * PR * 4);
                a[mt][2] = lds_u32(base + 16);
                a[mt][3] = lds_u32(base + 8 * PR * 4 + 16);
            }
            uint32_t b1v[2][2], b2v[2][2];
#pragma unroll
            for (int nt = 0; nt < 2; nt++) {
                uint32_t base1 = Bb + (uint32_t)((wn * 16 + nt * 8 + lq) * PR) * 4 + kcol;
                b1v[nt][0] = lds_u32(base1);
                b1v[nt][1] = lds_u32(base1 + 16);
                uint32_t base2 = base1 + 64 * PR * 4;
                b2v[nt][0] = lds_u32(base2);
                b2v[nt][1] = lds_u32(base2 + 16);
            }
#pragma unroll
            for (int mt = 0; mt < 8; mt++)
#pragma unroll
                for (int nt = 0; nt < 2; nt++) {
                    MMA_TF32(acc1[mt][nt], a[mt], b1v[nt][0], b1v[nt][1]);
                    MMA_TF32(acc2[mt][nt], a[mt], b2v[nt][0], b2v[nt][1]);
                }
        }
        // store prefetched into the other buffer
        if (kc + 1 < NC1) {
            uint32_t Ab2 = sb + (buf ^ 1) * STG;
            uint32_t Bb2 = Ab2 + A_BYTES;
#pragma unroll
            for (int p = 0; p < 8; p++) cvt_sts(Ab2 + p * 32 * PR * 4 + a_sts, va[p]);
#pragma unroll
            for (int p = 0; p < 4; p++) cvt_sts(Bb2 + p * 32 * PR * 4 + a_sts, vbr[p]);
        }
        __syncthreads();
    }

    // epilogue: silu fuse, write [m][n0..n0+63]
#pragma unroll
    for (int mt = 0; mt < 8; mt++) {
        int rbase = m0 + wm * 128 + mt * 16 + lq;
#pragma unroll
        for (int nt = 0; nt < 2; nt++) {
            int col = n0 + wn * 16 + nt * 8 + lr * 2;
#pragma unroll
            for (int half = 0; half < 2; half++) {
                int r = rbase + half * 8;
                if (r < M) {
                    float g1a = acc1[mt][nt][half * 2 + 0];
                    float g1b = acc1[mt][nt][half * 2 + 1];
                    float g2a = acc2[mt][nt][half * 2 + 0];
                    float g2b = acc2[mt][nt][half * 2 + 1];
                    float2 o;
                    o.x = g1a * (g2a / (1.f + expf(-g2a)));
                    o.y = g1b * (g2b / (1.f + expf(-g2b)));
                    *(float2*)&Out[(size_t)r * I1 + col] = o;
                }
            }
        }
    }
}

// ---------------- GEMM2 (tf32 mma.sync): Out[m][n] = G[m,:I1] . W[n,:I1] ----
__global__ __launch_bounds__(256, 1)
void gemm2_mma(const float* __restrict__ Wd, float* __restrict__ dout, int shared_mode) {
    int e = blockIdx.z;
    int M; const float* G; const float* Wp; float* Out;
    if (shared_mode) { M = S_TOK; G = &g_sh_gated[0][0]; Wp = Wd; Out = dout; }
    else {
        M = g_ecount[e]; G = &g_ex_gated[e][0][0];
        Wp = Wd + (size_t)e * HID * I1; Out = &g_ex_out[e][0][0];
    }
    int m0 = blockIdx.y * BM;
    if (m0 >= M) return;
    int n0 = blockIdx.x * 64;

    uint32_t sb = smem_u32(dsm);
    int t = threadIdx.x, lane = t & 31, wid = t >> 5;
    int wm = wid >> 2, wn = wid & 3;
    int lq = lane >> 2, lr = lane & 3;

    int kseg = t & 7;
    int r8   = t >> 3;

    const float* ap[8];
#pragma unroll
    for (int p = 0; p < 8; p++) {
        int m = m0 + p * 32 + r8;
        ap[p] = (m < M) ? (G + (size_t)m * I1 + kseg * 4) : nullptr;
    }
    const float* bp[2];
#pragma unroll
    for (int p = 0; p < 2; p++)
        bp[p] = Wp + (size_t)(n0 + p * 32 + r8) * I1 + kseg * 4;

    float acc[8][2][4];
#pragma unroll
    for (int mt = 0; mt < 8; mt++)
#pragma unroll
        for (int nt = 0; nt < 2; nt++)
#pragma unroll
            for (int i = 0; i < 4; i++) acc[mt][nt][i] = 0.f;

    float4 va[8], vbr[2];
    uint32_t a_sts = (uint32_t)(r8 * PR + kseg * 4) * 4;

#pragma unroll
    for (int p = 0; p < 8; p++)
        va[p] = ap[p] ? *(const float4*)(ap[p]) : make_float4(0.f, 0.f, 0.f, 0.f);
#pragma unroll
    for (int p = 0; p < 2; p++) vbr[p] = *(const float4*)(bp[p]);
    {
        uint32_t Ab = sb, Bb = sb + A_BYTES;
#pragma unroll
        for (int p = 0; p < 8; p++) cvt_sts(Ab + p * 32 * PR * 4 + a_sts, va[p]);
#pragma unroll
        for (int p = 0; p < 2; p++) cvt_sts(Bb + p * 32 * PR * 4 + a_sts, vbr[p]);
    }
    __syncthreads();

#pragma unroll 1
    for (int kc = 0; kc < NC2; kc++) {
        int buf = kc & 1;
        if (kc + 1 < NC2) {
            int ko = (kc + 1) * BK;
#pragma unroll
            for (int p = 0; p < 8; p++)
                va[p] = ap[p] ? *(const float4*)(ap[p] + ko) : make_float4(0.f, 0.f, 0.f, 0.f);
#pragma unroll
            for (int p = 0; p < 2; p++) vbr[p] = *(const float4*)(bp[p] + ko);
        }
        uint32_t Ab = sb + buf * STG;
        uint32_t Bb = Ab + A_BYTES;
#pragma unroll
        for (int ks = 0; ks < 4; ks++) {
            uint32_t kcol = (uint32_t)(ks * 8 + lr) * 4;
            uint32_t a[8][4];
#pragma unroll
            for (int mt = 0; mt < 8; mt++) {
                uint32_t base = Ab + (uint32_t)((wm * 128 + mt * 16 + lq) * PR) * 4 + kcol;
                a[mt][0] = lds_u32(base);
                a[mt][1] = lds_u32(base + 8 * PR * 4);
                a[mt][2] = lds_u32(base + 16);
                a[mt][3] = lds_u32(base + 8 * PR * 4 + 16);
            }
            uint32_t bv[2][2];
#pragma unroll
            for (int nt = 0; nt < 2; nt++) {
                uint32_t base = Bb + (uint32_t)((wn * 16 + nt * 8 + lq) * PR) * 4 + kcol;
                bv[nt][0] = lds_u32(base);
                bv[nt][1] = lds_u32(base + 16);
            }
#pragma unroll
            for (int mt = 0; mt < 8; mt++)
#pragma unroll
                for (int nt = 0; nt < 2; nt++)
                    MMA_TF32(acc[mt][nt], a[mt], bv[nt][0], bv[nt][1]);
        }
        if (kc + 1 < NC2) {
            uint32_t Ab2 = sb + (buf ^ 1) * STG;
            uint32_t Bb2 = Ab2 + A_BYTES;
#pragma unroll
            for (int p = 0; p < 8; p++) cvt_sts(Ab2 + p * 32 * PR * 4 + a_sts, va[p]);
#pragma unroll
            for (int p = 0; p < 2; p++) cvt_sts(Bb2 + p * 32 * PR * 4 + a_sts, vbr[p]);
        }
        __syncthreads();
    }

#pragma unroll
    for (int mt = 0; mt < 8; mt++) {
        int rbase = m0 + wm * 128 + mt * 16 + lq;
#pragma unroll
        for (int nt = 0; nt < 2; nt++) {
            int col = n0 + wn * 16 + nt * 8 + lr * 2;
#pragma unroll
            for (int half = 0; half < 2; half++) {
                int r = rbase + half * 8;
                if (r < M) {
                    float2 o;
                    o.x = acc[mt][nt][half * 2 + 0];
                    o.y = acc[mt][nt][half * 2 + 1];
                    *(float2*)&Out[(size_t)r * HID + col] = o;
                }
            }
        }
    }
}

// ---------------- combine ----------------
__global__ void combine_kernel(float* __restrict__ out) {
    int s = blockIdx.x, tid = threadIdx.x;
    __shared__ int ke[TK], kc_[TK];
    __shared__ float kw[TK];
    if (tid < TK) { ke[tid] = g_topi[s][tid]; kc_[tid] = g_slot[s][tid]; kw[tid] = g_topw[s][tid]; }
    __syncthreads();
    for (int h = tid; h < HID; h += 256) {
        float acc = out[(size_t)s * HID + h];
#pragma unroll
        for (int k = 0; k < TK; k++) {
            int c = kc_[k];
            if (c >= 0) acc += kw[k] * g_ex_out[ke[k]][c][h];
        }
        out[(size_t)s * HID + h] = acc;
    }
}

// ---------------------------------------------------------------------------
extern "C" void kernel_launch(void* const* d_in, const int* in_sizes, int n_in,
                              void* d_out, int out_size) {
    const float* x      = (const float*)d_in[0];
    const float* w_gu   = (const float*)d_in[1];
    const float* w_down = (const float*)d_in[2];
    const float* wg     = (const float*)d_in[3];
    const float* w1     = (const float*)d_in[4];
    const float* w2     = (const float*)d_in[5];
    const int*   cap    = (const int*)d_in[6];
    float* out = (float*)d_out;

    static int smem_set = 0;
    if (!smem_set) {
        cudaFuncSetAttribute(gemm1_mma, cudaFuncAttributeMaxDynamicSharedMemorySize, SMEM_BYTES);
        cudaFuncSetAttribute(gemm2_mma, cudaFuncAttributeMaxDynamicSharedMemorySize, SMEM_BYTES);
        smem_set = 1;
    }

    gating_kernel<<<S_TOK, 256>>>(x, wg);
    priority_kernel<<<NE, 32>>>(cap);

    { dim3 g(I1 / 64, S_TOK / BM, 1);   gemm1_mma<<<g, 256, SMEM_BYTES>>>(x, w_gu, 1); }
    { dim3 g(I1 / 64, 1, NE);           gemm1_mma<<<g, 256, SMEM_BYTES>>>(x, w1, 0); }
    { dim3 g(HID / 64, S_TOK / BM, 1);  gemm2_mma<<<g, 256, SMEM_BYTES>>>(w_down, out, 1); }
    { dim3 g(HID / 64, 1, NE);          gemm2_mma<<<g, 256, SMEM_BYTES>>>(w2, out, 0); }

    combine_kernel<<<S_TOK, 256>>>(out);
}

// round 4
// speedup vs baseline: 2.5919x; 1.1395x over previous
#include <cuda_runtime.h>
#include <cstdint>
#include <math.h>

// ---------------- problem constants ----------------
#define S_TOK   1024
#define HID     768
#define NE      64
#define TK      8
#define CAPMAX  256
#define I1      3072
#define I2      6144

// ---------------- GEMM tiling ----------------
#define BM   256
#define BK   32
#define PR   36                       // padded row length (floats)
#define A_BYTES (BM * PR * 4)         // 36864
#define B_BYTES (128 * PR * 4)        // 18432
#define STG     (A_BYTES + B_BYTES)   // 55296
#define SMEM_BYTES (2 * STG)          // 110592
#define NC1 (HID / BK)                // 24
#define NC2 (I1 / BK)                 // 96

// ---------------- device scratch ----------------
__device__ __align__(16)  float g_topw[S_TOK][TK];
__device__ __align__(16)  int   g_topi[S_TOK][TK];
__device__ __align__(16)  int   g_slot[S_TOK][TK];
__device__ __align__(16)  int   g_ecount[NE];
__device__ __align__(16)  int   g_etok[NE][CAPMAX];
__device__ __align__(256) float g_sh_gated[S_TOK][I1];
__device__ __align__(256) float g_ex_gated[NE][CAPMAX][I1];
__device__ __align__(256) float g_ex_out[NE][CAPMAX][HID];

// ---------------- helpers ----------------
__device__ __forceinline__ uint32_t smem_u32(const void* p) {
    uint32_t a;
    asm("{ .reg .u64 t; cvta.to.shared.u64 t, %1; cvt.u32.u64 %0, t; }" : "=r"(a) : "l"(p));
    return a;
}
__device__ __forceinline__ uint32_t lds_u32(uint32_t addr) {
    uint32_t v;
    asm volatile("ld.shared.b32 %0, [%1];" : "=r"(v) : "r"(addr));
    return v;
}
__device__ __forceinline__ void cvt_sts(uint32_t addr, float4 v) {
    uint32_t a, b, c, d;
    asm volatile("cvt.rna.tf32.f32 %0, %1;" : "=r"(a) : "f"(v.x));
    asm volatile("cvt.rna.tf32.f32 %0, %1;" : "=r"(b) : "f"(v.y));
    asm volatile("cvt.rna.tf32.f32 %0, %1;" : "=r"(c) : "f"(v.z));
    asm volatile("cvt.rna.tf32.f32 %0, %1;" : "=r"(d) : "f"(v.w));
    asm volatile("st.shared.v4.b32 [%0], {%1, %2, %3, %4};"
                 :: "r"(addr), "r"(a), "r"(b), "r"(c), "r"(d) : "memory");
}
#define MMA_TF32(c, a, b0v, b1v) \
    asm volatile("mma.sync.aligned.m16n8k8.row.col.f32.tf32.tf32.f32 " \
        "{%0,%1,%2,%3}, {%4,%5,%6,%7}, {%8,%9}, {%0,%1,%2,%3};" \
        : "+f"((c)[0]), "+f"((c)[1]), "+f"((c)[2]), "+f"((c)[3]) \
        : "r"((a)[0]), "r"((a)[1]), "r"((a)[2]), "r"((a)[3]), "r"(b0v), "r"(b1v))

extern __shared__ char dsm[];

// ---------------- gating ----------------
__global__ void gating_kernel(const float* __restrict__ x,
                              const float* __restrict__ wg) {
    int s = blockIdx.x;
    __shared__ float xs[HID];
    __shared__ float logits_s[NE];
    int tid = threadIdx.x;

    for (int i = tid; i < HID; i += 256) xs[i] = x[(size_t)s * HID + i];
    __syncthreads();

    int e = tid >> 2, sub = tid & 3;
    const float* w = wg + (size_t)e * HID;
    float acc = 0.f;
    for (int i = sub; i < HID; i += 4) acc += xs[i] * w[i];
    acc += __shfl_down_sync(0xffffffffu, acc, 2);
    acc += __shfl_down_sync(0xffffffffu, acc, 1);
    if (sub == 0) logits_s[e] = acc;
    __syncthreads();

    if (tid < 32) {
        float v0 = logits_s[tid];
        float v1 = logits_s[tid + 32];
        float tv[TK]; int tix[TK];
#pragma unroll
        for (int r = 0; r < TK; r++) {
            float bv; int bi;
            if (v0 >= v1) { bv = v0; bi = tid; }
            else          { bv = v1; bi = tid + 32; }
#pragma unroll
            for (int off = 16; off > 0; off >>= 1) {
                float ov = __shfl_down_sync(0xffffffffu, bv, off);
                int   oi = __shfl_down_sync(0xffffffffu, bi, off);
                if (ov > bv || (ov == bv && oi < bi)) { bv = ov; bi = oi; }
            }
            bv = __shfl_sync(0xffffffffu, bv, 0);
            bi = __shfl_sync(0xffffffffu, bi, 0);
            if (bi == tid)      v0 = -INFINITY;
            if (bi == tid + 32) v1 = -INFINITY;
            tv[r] = bv; tix[r] = bi;
        }
        if (tid == 0) {
            float m = tv[0], wv[TK], D = 0.f;
#pragma unroll
            for (int r = 0; r < TK; r++) { wv[r] = expf(tv[r] - m); D += wv[r]; }
            D = fmaxf(D, 1.1920929e-7f);
#pragma unroll
            for (int r = 0; r < TK; r++) { g_topw[s][r] = wv[r] / D; g_topi[s][r] = tix[r]; }
        }
    }
}

// ---------------- priority ----------------
__global__ void priority_kernel(const int* __restrict__ capacity) {
    int e = blockIdx.x, lane = threadIdx.x;
    int cap = capacity[0];
    if (cap > CAPMAX) cap = CAPMAX;
    if (cap < 0) cap = 0;

    int offset = 0;
    for (int base = 0; base < S_TOK * TK; base += 32) {
        int p = base + lane;
        int k = p / S_TOK;
        int s = p - k * S_TOK;
        bool match = (g_topi[s][k] == e);
        unsigned mask = __ballot_sync(0xffffffffu, match);
        if (match) {
            int c = offset + __popc(mask & ((1u << lane) - 1u));
            if (c < cap) { g_slot[s][k] = c; g_etok[e][c] = s; }
            else         { g_slot[s][k] = -1; }
        }
        offset += __popc(mask);
    }
    if (lane == 0) g_ecount[e] = (offset < cap) ? offset : cap;
}

// ---------------- GEMM1 (tf32 mma.sync, 512 thr) + fused SwiGLU ----------------
// Block: 256 rows x 64 output cols; B smem rows 0..63 = g1 W rows, 64..127 = g2.
__global__ __launch_bounds__(512, 1)
void gemm1_mma(const float* __restrict__ X, const float* __restrict__ W, int shared_mode) {
    int e = blockIdx.z;
    int M; const int* gather; const float* Wp; float* Out;
    if (shared_mode) { M = S_TOK; gather = nullptr; Wp = W; Out = &g_sh_gated[0][0]; }
    else {
        M = g_ecount[e]; gather = g_etok[e];
        Wp = W + (size_t)e * I2 * HID; Out = &g_ex_gated[e][0][0];
    }
    int m0 = blockIdx.y * BM;
    if (m0 >= M) return;
    int n0 = blockIdx.x * 64;

    uint32_t sb = smem_u32(dsm);
    int t = threadIdx.x, lane = t & 31, wid = t >> 5;
    int wm = wid >> 2, wn = wid & 3;     // 4 x 4 warp grid
    int lq = lane >> 2, lr = lane & 3;

    int kseg = t & 7;           // k offset kseg*4
    int r64  = t >> 3;          // 0..63

    // A: 4 passes of 64 rows
    const float* ap[4];
#pragma unroll
    for (int p = 0; p < 4; p++) {
        int m = m0 + p * 64 + r64;
        ap[p] = (m < M) ? (X + (size_t)(gather ? gather[m] : m) * HID + kseg * 4) : nullptr;
    }
    // B: 2 passes of 64 rows (pass0 -> g1, pass1 -> g2)
    const float* bp[2];
    bp[0] = Wp + (size_t)(n0 + r64) * HID + kseg * 4;
    bp[1] = Wp + (size_t)(I1 + n0 + r64) * HID + kseg * 4;

    float acc1[4][2][4], acc2[4][2][4];
#pragma unroll
    for (int mt = 0; mt < 4; mt++)
#pragma unroll
        for (int nt = 0; nt < 2; nt++)
#pragma unroll
            for (int i = 0; i < 4; i++) { acc1[mt][nt][i] = 0.f; acc2[mt][nt][i] = 0.f; }

    float4 va[4], vbr[2];
    uint32_t sts_off = (uint32_t)(r64 * PR + kseg * 4) * 4;

    // prologue
#pragma unroll
    for (int p = 0; p < 4; p++)
        va[p] = ap[p] ? *(const float4*)(ap[p]) : make_float4(0.f, 0.f, 0.f, 0.f);
#pragma unroll
    for (int p = 0; p < 2; p++) vbr[p] = *(const float4*)(bp[p]);
    {
        uint32_t Ab = sb, Bb = sb + A_BYTES;
#pragma unroll
        for (int p = 0; p < 4; p++) cvt_sts(Ab + p * 64 * PR * 4 + sts_off, va[p]);
#pragma unroll
        for (int p = 0; p < 2; p++) cvt_sts(Bb + p * 64 * PR * 4 + sts_off, vbr[p]);
    }
    __syncthreads();

#pragma unroll 1
    for (int kc = 0; kc < NC1; kc++) {
        int buf = kc & 1;
        if (kc + 1 < NC1) {
            int ko = (kc + 1) * BK;
#pragma unroll
            for (int p = 0; p < 4; p++)
                va[p] = ap[p] ? *(const float4*)(ap[p] + ko) : make_float4(0.f, 0.f, 0.f, 0.f);
#pragma unroll
            for (int p = 0; p < 2; p++) vbr[p] = *(const float4*)(bp[p] + ko);
        }
        uint32_t Ab = sb + buf * STG;
        uint32_t Bb = Ab + A_BYTES;
#pragma unroll
        for (int ks = 0; ks < 4; ks++) {
            uint32_t kcol = (uint32_t)(ks * 8 + lr) * 4;
            uint32_t b1v[2][2], b2v[2][2];
#pragma unroll
            for (int nt = 0; nt < 2; nt++) {
                uint32_t base1 = Bb + (uint32_t)((wn * 16 + nt * 8 + lq) * PR) * 4 + kcol;
                b1v[nt][0] = lds_u32(base1);
                b1v[nt][1] = lds_u32(base1 + 16);
                uint32_t base2 = base1 + 64 * PR * 4;
                b2v[nt][0] = lds_u32(base2);
                b2v[nt][1] = lds_u32(base2 + 16);
            }
#pragma unroll
            for (int mt = 0; mt < 4; mt++) {
                uint32_t a[4];
                uint32_t base = Ab + (uint32_t)((wm * 64 + mt * 16 + lq) * PR) * 4 + kcol;
                a[0] = lds_u32(base);
                a[1] = lds_u32(base + 8 * PR * 4);
                a[2] = lds_u32(base + 16);
                a[3] = lds_u32(base + 8 * PR * 4 + 16);
#pragma unroll
                for (int nt = 0; nt < 2; nt++) {
                    MMA_TF32(acc1[mt][nt], a, b1v[nt][0], b1v[nt][1]);
                    MMA_TF32(acc2[mt][nt], a, b2v[nt][0], b2v[nt][1]);
                }
            }
        }
        if (kc + 1 < NC1) {
            uint32_t Ab2 = sb + (buf ^ 1) * STG;
            uint32_t Bb2 = Ab2 + A_BYTES;
#pragma unroll
            for (int p = 0; p < 4; p++) cvt_sts(Ab2 + p * 64 * PR * 4 + sts_off, va[p]);
#pragma unroll
            for (int p = 0; p < 2; p++) cvt_sts(Bb2 + p * 64 * PR * 4 + sts_off, vbr[p]);
        }
        __syncthreads();
    }

    // epilogue: fused SwiGLU
#pragma unroll
    for (int mt = 0; mt < 4; mt++) {
        int rbase = m0 + wm * 64 + mt * 16 + lq;
#pragma unroll
        for (int nt = 0; nt < 2; nt++) {
            int col = n0 + wn * 16 + nt * 8 + lr * 2;
#pragma unroll
            for (int half = 0; half < 2; half++) {
                int r = rbase + half * 8;
                if (r < M) {
                    float g1a = acc1[mt][nt][half * 2 + 0];
                    float g1b = acc1[mt][nt][half * 2 + 1];
                    float g2a = acc2[mt][nt][half * 2 + 0];
                    float g2b = acc2[mt][nt][half * 2 + 1];
                    float2 o;
                    o.x = g1a * (g2a / (1.f + expf(-g2a)));
                    o.y = g1b * (g2b / (1.f + expf(-g2b)));
                    *(float2*)&Out[(size_t)r * I1 + col] = o;
                }
            }
        }
    }
}

// ---------------- GEMM2 (tf32 mma.sync, 512 thr): 256 x 128 tile ----------------
__global__ __launch_bounds__(512, 1)
void gemm2_mma(const float* __restrict__ Wd, float* __restrict__ dout, int shared_mode) {
    int e = blockIdx.z;
    int M; const float* G; const float* Wp; float* Out;
    if (shared_mode) { M = S_TOK; G = &g_sh_gated[0][0]; Wp = Wd; Out = dout; }
    else {
        M = g_ecount[e]; G = &g_ex_gated[e][0][0];
        Wp = Wd + (size_t)e * HID * I1; Out = &g_ex_out[e][0][0];
    }
    int m0 = blockIdx.y * BM;
    if (m0 >= M) return;
    int n0 = blockIdx.x * 128;

    uint32_t sb = smem_u32(dsm);
    int t = threadIdx.x, lane = t & 31, wid = t >> 5;
    int wm = wid >> 2, wn = wid & 3;
    int lq = lane >> 2, lr = lane & 3;

    int kseg = t & 7;
    int r64  = t >> 3;

    const float* ap[4];
#pragma unroll
    for (int p = 0; p < 4; p++) {
        int m = m0 + p * 64 + r64;
        ap[p] = (m < M) ? (G + (size_t)m * I1 + kseg * 4) : nullptr;
    }
    const float* bp[2];
    bp[0] = Wp + (size_t)(n0 + r64) * I1 + kseg * 4;
    bp[1] = Wp + (size_t)(n0 + 64 + r64) * I1 + kseg * 4;

    float acc[4][4][4];
#pragma unroll
    for (int mt = 0; mt < 4; mt++)
#pragma unroll
        for (int nt = 0; nt < 4; nt++)
#pragma unroll
            for (int i = 0; i < 4; i++) acc[mt][nt][i] = 0.f;

    float4 va[4], vbr[2];
    uint32_t sts_off = (uint32_t)(r64 * PR + kseg * 4) * 4;

#pragma unroll
    for (int p = 0; p < 4; p++)
        va[p] = ap[p] ? *(const float4*)(ap[p]) : make_float4(0.f, 0.f, 0.f, 0.f);
#pragma unroll
    for (int p = 0; p < 2; p++) vbr[p] = *(const float4*)(bp[p]);
    {
        uint32_t Ab = sb, Bb = sb + A_BYTES;
#pragma unroll
        for (int p = 0; p < 4; p++) cvt_sts(Ab + p * 64 * PR * 4 + sts_off, va[p]);
#pragma unroll
        for (int p = 0; p < 2; p++) cvt_sts(Bb + p * 64 * PR * 4 + sts_off, vbr[p]);
    }
    __syncthreads();

#pragma unroll 1
    for (int kc = 0; kc < NC2; kc++) {
        int buf = kc & 1;
        if (kc + 1 < NC2) {
            int ko = (kc + 1) * BK;
#pragma unroll
            for (int p = 0; p < 4; p++)
                va[p] = ap[p] ? *(const float4*)(ap[p] + ko) : make_float4(0.f, 0.f, 0.f, 0.f);
#pragma unroll
            for (int p = 0; p < 2; p++) vbr[p] = *(const float4*)(bp[p] + ko);
        }
        uint32_t Ab = sb + buf * STG;
        uint32_t Bb = Ab + A_BYTES;
#pragma unroll
        for (int ks = 0; ks < 4; ks++) {
            uint32_t kcol = (uint32_t)(ks * 8 + lr) * 4;
            uint32_t bv[4][2];
#pragma unroll
            for (int nt = 0; nt < 4; nt++) {
                uint32_t base = Bb + (uint32_t)((wn * 32 + nt * 8 + lq) * PR) * 4 + kcol;
                bv[nt][0] = lds_u32(base);
                bv[nt][1] = lds_u32(base + 16);
            }
#pragma unroll
            for (int mt = 0; mt < 4; mt++) {
                uint32_t a[4];
                uint32_t base = Ab + (uint32_t)((wm * 64 + mt * 16 + lq) * PR) * 4 + kcol;
                a[0] = lds_u32(base);
                a[1] = lds_u32(base + 8 * PR * 4);
                a[2] = lds_u32(base + 16);
                a[3] = lds_u32(base + 8 * PR * 4 + 16);
#pragma unroll
                for (int nt = 0; nt < 4; nt++)
                    MMA_TF32(acc[mt][nt], a, bv[nt][0], bv[nt][1]);
            }
        }
        if (kc + 1 < NC2) {
            uint32_t Ab2 = sb + (buf ^ 1) * STG;
            uint32_t Bb2 = Ab2 + A_BYTES;
#pragma unroll
            for (int p = 0; p < 4; p++) cvt_sts(Ab2 + p * 64 * PR * 4 + sts_off, va[p]);
#pragma unroll
            for (int p = 0; p < 2; p++) cvt_sts(Bb2 + p * 64 * PR * 4 + sts_off, vbr[p]);
        }
        __syncthreads();
    }

#pragma unroll
    for (int mt = 0; mt < 4; mt++) {
        int rbase = m0 + wm * 64 + mt * 16 + lq;
#pragma unroll
        for (int nt = 0; nt < 4; nt++) {
            int col = n0 + wn * 32 + nt * 8 + lr * 2;
#pragma unroll
            for (int half = 0; half < 2; half++) {
                int r = rbase + half * 8;
                if (r < M) {
                    float2 o;
                    o.x = acc[mt][nt][half * 2 + 0];
                    o.y = acc[mt][nt][half * 2 + 1];
                    *(float2*)&Out[(size_t)r * HID + col] = o;
                }
            }
        }
    }
}

// ---------------- combine ----------------
__global__ void combine_kernel(float* __restrict__ out) {
    int s = blockIdx.x, tid = threadIdx.x;
    __shared__ int ke[TK], kc_[TK];
    __shared__ float kw[TK];
    if (tid < TK) { ke[tid] = g_topi[s][tid]; kc_[tid] = g_slot[s][tid]; kw[tid] = g_topw[s][tid]; }
    __syncthreads();
    for (int h = tid; h < HID; h += 256) {
        float acc = out[(size_t)s * HID + h];
#pragma unroll
        for (int k = 0; k < TK; k++) {
            int c = kc_[k];
            if (c >= 0) acc += kw[k] * g_ex_out[ke[k]][c][h];
        }
        out[(size_t)s * HID + h] = acc;
    }
}

// ---------------------------------------------------------------------------
extern "C" void kernel_launch(void* const* d_in, const int* in_sizes, int n_in,
                              void* d_out, int out_size) {
    const float* x      = (const float*)d_in[0];
    const float* w_gu   = (const float*)d_in[1];
    const float* w_down = (const float*)d_in[2];
    const float* wg     = (const float*)d_in[3];
    const float* w1     = (const float*)d_in[4];
    const float* w2     = (const float*)d_in[5];
    const int*   cap    = (const int*)d_in[6];
    float* out = (float*)d_out;

    cudaFuncSetAttribute(gemm1_mma, cudaFuncAttributeMaxDynamicSharedMemorySize, SMEM_BYTES);
    cudaFuncSetAttribute(gemm2_mma, cudaFuncAttributeMaxDynamicSharedMemorySize, SMEM_BYTES);

    gating_kernel<<<S_TOK, 256>>>(x, wg);
    priority_kernel<<<NE, 32>>>(cap);

    { dim3 g(I1 / 64, S_TOK / BM, 1);    gemm1_mma<<<g, 512, SMEM_BYTES>>>(x, w_gu, 1); }
    { dim3 g(I1 / 64, 1, NE);            gemm1_mma<<<g, 512, SMEM_BYTES>>>(x, w1, 0); }
    { dim3 g(HID / 128, S_TOK / BM, 1);  gemm2_mma<<<g, 512, SMEM_BYTES>>>(w_down, out, 1); }
    { dim3 g(HID / 128, 1, NE);          gemm2_mma<<<g, 512, SMEM_BYTES>>>(w2, out, 0); }

    combine_kernel<<<S_TOK, 256>>>(out);
}